// round 1
// baseline (speedup 1.0000x reference)
#include <cuda_runtime.h>
#include <math.h>

// ---------------------------------------------------------------------------
// Problem constants
//   B=2, H=W=512.  Three image variants (iout, igt, icomp) -> 6 NCHW images.
//   Variant-major image index: n = v*2 + b, v: 0=out, 1=gt, 2=comp.
// ---------------------------------------------------------------------------
#define HW0 (512*512)

// Scratch (static device globals; no runtime allocation allowed)
__device__ float g_x0  [6*3*HW0];          //  18.9 MB  input stack
__device__ float g_bufA[6*64*HW0];         // 402.7 MB  ping
__device__ float g_bufB[6*64*HW0];         // 402.7 MB  pong
__device__ float g_p1  [6*64*256*256];     // 100.7 MB  pool1
__device__ float g_p2  [6*128*128*128];    //  50.3 MB  pool2
__device__ float g_p3  [6*256*64*64];      //  25.2 MB  pool3
__device__ double g_acc[4];                // 0:hole 1:valid 2:perc(raw) 3:style(scaled)

// ---------------------------------------------------------------------------
__device__ __forceinline__ double blockReduceSum(double v) {
    __shared__ double s[32];
    int lane = threadIdx.x & 31;
    int wid  = threadIdx.x >> 5;
    #pragma unroll
    for (int o = 16; o; o >>= 1) v += __shfl_down_sync(0xffffffffu, v, o);
    if (lane == 0) s[wid] = v;
    __syncthreads();
    int nw = blockDim.x >> 5;
    v = (threadIdx.x < nw) ? s[threadIdx.x] : 0.0;
    if (wid == 0) {
        #pragma unroll
        for (int o = 16; o; o >>= 1) v += __shfl_down_sync(0xffffffffu, v, o);
    }
    return v;
}

__global__ void zero_acc() {
    if (threadIdx.x < 4) g_acc[threadIdx.x] = 0.0;
}

// ---------------------------------------------------------------------------
// Build x0 = [iout(2), igt(2), icomp(2)] and accumulate hole/valid L1 sums.
// ---------------------------------------------------------------------------
__global__ void prep_kernel(const float* __restrict__ igt,
                            const float* __restrict__ iout,
                            const float* __restrict__ mask) {
    double hole = 0.0, valid = 0.0;
    const int total = 2*3*HW0;
    int stride = gridDim.x * blockDim.x;
    for (int i = blockIdx.x*blockDim.x + threadIdx.x; i < total; i += stride) {
        int hw = i % HW0;
        int t  = i / HW0;          // b*3 + c
        int b  = t / 3;
        float g  = igt[i];
        float o  = iout[i];
        float mv = mask[b*HW0 + hw];
        float ad = fabsf(o - g);
        bool m = (mv != 0.0f);
        if (m) valid += (double)ad; else hole += (double)ad;
        float comp = m ? g : o;
        g_x0[i]            = o;     // n = b      (out)
        g_x0[i + 6*HW0]    = g;     // n = 2+b    (gt)
        g_x0[i + 12*HW0]   = comp;  // n = 4+b    (comp)
    }
    hole  = blockReduceSum(hole);
    __syncthreads();
    valid = blockReduceSum(valid);
    if (threadIdx.x == 0) {
        atomicAdd(&g_acc[0], hole);
        atomicAdd(&g_acc[1], valid);
    }
}

// ---------------------------------------------------------------------------
// Direct 3x3 SAME conv + bias + ReLU, NCHW, N=6 images.
// Block: 256 threads; output tile 16(h) x 64(w); 8 output channels per block.
// Each thread: 4 consecutive w pixels x 8 couts = 32 accumulators.
// ---------------------------------------------------------------------------
__global__ __launch_bounds__(256, 2)
void conv3x3_relu(const float* __restrict__ in, const float* __restrict__ wgt,
                  const float* __restrict__ bias, float* __restrict__ out,
                  int CIN, int COUT, int S)
{
    const int tid = threadIdx.x;
    const int tx = tid & 15;        // w group (4 px each)
    const int ty = tid >> 4;        // row within tile
    const int ncog = COUT >> 3;
    const int n   = blockIdx.z / ncog;
    const int cog = blockIdx.z % ncog;
    const int w0 = blockIdx.x * 64;
    const int h0 = blockIdx.y * 16;

    __shared__ __align__(16) float s_in[2][18][68];   // halo tile, padded stride
    __shared__ float s_w[2][8][9];

    float acc[8][4];
    #pragma unroll
    for (int a = 0; a < 8; a++) { acc[a][0]=acc[a][1]=acc[a][2]=acc[a][3]=0.f; }

    const float* inb = in  + (size_t)n * CIN * S * S;
    const float* wb  = wgt + (size_t)(cog*8) * CIN * 9;

    for (int c0 = 0; c0 < CIN; c0 += 2) {
        const int nc = (CIN - c0) >= 2 ? 2 : 1;
        __syncthreads();
        for (int ci = 0; ci < nc; ci++) {
            const float* src = inb + (size_t)(c0+ci)*S*S;
            for (int i = tid; i < 18*66; i += 256) {
                int r  = i / 66;
                int cc = i - r*66;
                int h = h0 + r - 1;
                int w = w0 + cc - 1;
                float v = 0.f;
                if ((unsigned)h < (unsigned)S && (unsigned)w < (unsigned)S)
                    v = src[h*S + w];
                s_in[ci][r][cc] = v;
            }
        }
        for (int i = tid; i < 8*nc*9; i += 256) {
            int co  = i / (nc*9);
            int rem = i - co*nc*9;
            int ci  = rem / 9;
            int k   = rem - ci*9;
            s_w[ci][co][k] = wb[(size_t)co*CIN*9 + (size_t)(c0+ci)*9 + k];
        }
        __syncthreads();
        #pragma unroll
        for (int ci = 0; ci < 2; ci++) {
            if (ci < nc) {
                #pragma unroll
                for (int dy = 0; dy < 3; dy++) {
                    const int r = ty + dy;
                    float vv[6];
                    float4 q = *(const float4*)&s_in[ci][r][tx*4];
                    vv[0]=q.x; vv[1]=q.y; vv[2]=q.z; vv[3]=q.w;
                    vv[4] = s_in[ci][r][tx*4+4];
                    vv[5] = s_in[ci][r][tx*4+5];
                    #pragma unroll
                    for (int dx = 0; dx < 3; dx++) {
                        #pragma unroll
                        for (int co = 0; co < 8; co++) {
                            float wv = s_w[ci][co][dy*3+dx];
                            acc[co][0] = fmaf(vv[dx+0], wv, acc[co][0]);
                            acc[co][1] = fmaf(vv[dx+1], wv, acc[co][1]);
                            acc[co][2] = fmaf(vv[dx+2], wv, acc[co][2]);
                            acc[co][3] = fmaf(vv[dx+3], wv, acc[co][3]);
                        }
                    }
                }
            }
        }
    }

    const int h = h0 + ty;
    const int w = w0 + tx*4;
    #pragma unroll
    for (int co = 0; co < 8; co++) {
        float bv = bias[cog*8+co];
        float4 o;
        o.x = fmaxf(acc[co][0]+bv, 0.f);
        o.y = fmaxf(acc[co][1]+bv, 0.f);
        o.z = fmaxf(acc[co][2]+bv, 0.f);
        o.w = fmaxf(acc[co][3]+bv, 0.f);
        *(float4*)&out[((size_t)(n*COUT + cog*8+co)*S + h)*S + w] = o;
    }
}

// ---------------------------------------------------------------------------
// 2x2 stride-2 max pool, NCHW, N=6.
// ---------------------------------------------------------------------------
__global__ void maxpool2(const float* __restrict__ in, float* __restrict__ out,
                         int C, int S) {
    const int So = S >> 1;
    const size_t total = (size_t)6*C*So*So;
    const size_t stride = (size_t)gridDim.x * blockDim.x;
    for (size_t i = blockIdx.x*(size_t)blockDim.x + threadIdx.x; i < total; i += stride) {
        int x = (int)(i % So);
        size_t t = i / So;
        int y = (int)(t % So);
        size_t ncc = t / So;
        const float* p = in + (ncc*S + 2*y)*S + 2*x;
        out[i] = fmaxf(fmaxf(p[0], p[1]), fmaxf(p[S], p[S+1]));
    }
}

// ---------------------------------------------------------------------------
// Perceptual L1 sums: sum |out-gt| + |comp-gt| over one pool level (raw).
// ---------------------------------------------------------------------------
__global__ void perc_kernel(const float* __restrict__ p, int C, int S) {
    const size_t per = (size_t)C*S*S;
    const size_t total = 2*per;
    const size_t stride = (size_t)gridDim.x * blockDim.x;
    double s = 0.0;
    for (size_t i = blockIdx.x*(size_t)blockDim.x + threadIdx.x; i < total; i += stride) {
        float po = p[i];              // n = b
        float pg = p[i + 2*per];      // n = 2+b
        float pc = p[i + 4*per];      // n = 4+b
        s += (double)(fabsf(po-pg) + fabsf(pc-pg));
    }
    s = blockReduceSum(s);
    if (threadIdx.x == 0) atomicAdd(&g_acc[2], s);
}

// ---------------------------------------------------------------------------
// Style: per (b,c) WxW Gram (contraction over h), fused |Ga-Gg| reduction.
// Block computes a 64x64 (w,v) tile of both Grams; thread = 4x4 microtile x2.
// ---------------------------------------------------------------------------
__global__ __launch_bounds__(256, 2)
void style_kernel(const float* __restrict__ p, int C, int S, int va, double scale) {
    const int tid = threadIdx.x;
    const int tx = tid & 15, ty = tid >> 4;
    const int bc = blockIdx.z;
    const int b = bc / C, c = bc - b*C;
    const int wt = blockIdx.y * 64;
    const int vt = blockIdx.x * 64;
    const float* A = p + ((size_t)((va*2+b)*C + c)) * S * S;
    const float* G = p + ((size_t)((2   +b)*C + c)) * S * S;

    __shared__ __align__(16) float s_aw[32][64], s_av[32][64];
    __shared__ __align__(16) float s_gw[32][64], s_gv[32][64];

    float accA[4][4], accG[4][4];
    #pragma unroll
    for (int i = 0; i < 4; i++)
        #pragma unroll
        for (int j = 0; j < 4; j++) { accA[i][j] = 0.f; accG[i][j] = 0.f; }

    for (int k0 = 0; k0 < S; k0 += 32) {
        __syncthreads();
        for (int i = tid; i < 32*64; i += 256) {
            int kk  = i >> 6;
            int col = i & 63;
            size_t row = (size_t)(k0+kk)*S;
            s_aw[kk][col] = A[row + wt + col];
            s_av[kk][col] = A[row + vt + col];
            s_gw[kk][col] = G[row + wt + col];
            s_gv[kk][col] = G[row + vt + col];
        }
        __syncthreads();
        #pragma unroll 4
        for (int kk = 0; kk < 32; kk++) {
            float4 aw4 = *(const float4*)&s_aw[kk][ty*4];
            float4 av4 = *(const float4*)&s_av[kk][tx*4];
            float4 gw4 = *(const float4*)&s_gw[kk][ty*4];
            float4 gv4 = *(const float4*)&s_gv[kk][tx*4];
            float aw[4] = {aw4.x,aw4.y,aw4.z,aw4.w};
            float av[4] = {av4.x,av4.y,av4.z,av4.w};
            float gw[4] = {gw4.x,gw4.y,gw4.z,gw4.w};
            float gv[4] = {gv4.x,gv4.y,gv4.z,gv4.w};
            #pragma unroll
            for (int i = 0; i < 4; i++)
                #pragma unroll
                for (int j = 0; j < 4; j++) {
                    accA[i][j] = fmaf(aw[i], av[j], accA[i][j]);
                    accG[i][j] = fmaf(gw[i], gv[j], accG[i][j]);
                }
        }
    }
    double s = 0.0;
    #pragma unroll
    for (int i = 0; i < 4; i++)
        #pragma unroll
        for (int j = 0; j < 4; j++)
            s += (double)fabsf(accA[i][j] - accG[i][j]);
    s = blockReduceSum(s);
    if (threadIdx.x == 0) atomicAdd(&g_acc[3], scale * s);
}

// ---------------------------------------------------------------------------
__global__ void finish_kernel(float* __restrict__ out) {
    const double N    = 3.0*512.0*512.0*2.0;      // 3*H*W*B
    const double Nigt = 2.0*64.0*256.0*256.0;     // prod(pool_gt[0].shape) (faithful)
    double t = 2.0*g_acc[0]/N     // l_hole: *B over full norm (faithful)
             +     g_acc[1]/N     // l_valid
             +     g_acc[2]/Nigt  // l_perc
             +     g_acc[3];      // styles (pre-scaled)
    out[0] = (float)t;
}

// ---------------------------------------------------------------------------
extern "C" void kernel_launch(void* const* d_in, const int* in_sizes, int n_in,
                              void* d_out, int out_size) {
    const float* igt  = (const float*)d_in[0];
    const float* iout = (const float*)d_in[1];
    const float* mask = (const float*)d_in[2];
    const float* w[7]; const float* bs[7];
    for (int i = 0; i < 7; i++) {
        w[i]  = (const float*)d_in[3 + 2*i];
        bs[i] = (const float*)d_in[4 + 2*i];
    }

    float *x0, *bufA, *bufB, *p1, *p2, *p3;
    cudaGetSymbolAddress((void**)&x0,   g_x0);
    cudaGetSymbolAddress((void**)&bufA, g_bufA);
    cudaGetSymbolAddress((void**)&bufB, g_bufB);
    cudaGetSymbolAddress((void**)&p1,   g_p1);
    cudaGetSymbolAddress((void**)&p2,   g_p2);
    cudaGetSymbolAddress((void**)&p3,   g_p3);

    zero_acc<<<1, 32>>>();
    prep_kernel<<<2048, 256>>>(igt, iout, mask);

    // VGG stack on 6 images
    conv3x3_relu<<<dim3(8,32, 48), 256>>>(x0,   w[0], bs[0], bufA,   3,  64, 512);
    conv3x3_relu<<<dim3(8,32, 48), 256>>>(bufA, w[1], bs[1], bufB,  64,  64, 512);
    maxpool2<<<4096, 256>>>(bufB, p1, 64, 512);
    conv3x3_relu<<<dim3(4,16, 96), 256>>>(p1,   w[2], bs[2], bufA,  64, 128, 256);
    conv3x3_relu<<<dim3(4,16, 96), 256>>>(bufA, w[3], bs[3], bufB, 128, 128, 256);
    maxpool2<<<2048, 256>>>(bufB, p2, 128, 256);
    conv3x3_relu<<<dim3(2, 8,192), 256>>>(p2,   w[4], bs[4], bufA, 128, 256, 128);
    conv3x3_relu<<<dim3(2, 8,192), 256>>>(bufA, w[5], bs[5], bufB, 256, 256, 128);
    conv3x3_relu<<<dim3(2, 8,192), 256>>>(bufB, w[6], bs[6], bufA, 256, 256, 128);
    maxpool2<<<1024, 256>>>(bufA, p3, 256, 128);

    // Perceptual sums (raw; /Nigt in finish)
    perc_kernel<<<2048, 256>>>(p1,  64, 256);
    perc_kernel<<<2048, 256>>>(p2, 128, 128);
    perc_kernel<<<1024, 256>>>(p3, 256,  64);

    // Style: scale = Kp / C^2 = 1/(C*H*W*C*C)
    const double s1 = 1.0/((double)64 *256*256)/( 64.0* 64.0);
    const double s2 = 1.0/((double)128*128*128)/(128.0*128.0);
    const double s3 = 1.0/((double)256* 64* 64)/(256.0*256.0);
    style_kernel<<<dim3(4,4,128), 256>>>(p1,  64, 256, 2, s1);  // comp vs gt
    style_kernel<<<dim3(4,4,128), 256>>>(p1,  64, 256, 0, s1);  // out  vs gt
    style_kernel<<<dim3(2,2,256), 256>>>(p2, 128, 128, 2, s2);
    style_kernel<<<dim3(2,2,256), 256>>>(p2, 128, 128, 0, s2);
    style_kernel<<<dim3(1,1,512), 256>>>(p3, 256,  64, 2, s3);
    style_kernel<<<dim3(1,1,512), 256>>>(p3, 256,  64, 0, s3);

    finish_kernel<<<1, 1>>>((float*)d_out);
}

// round 2
// speedup vs baseline: 1.8171x; 1.8171x over previous
#include <cuda_runtime.h>
#include <math.h>
#include <stdint.h>

// ---------------------------------------------------------------------------
// B=2, H=W=512. Three variants (iout, igt, icomp) -> 6 NCHW images.
// n = v*2 + b, v: 0=out, 1=gt, 2=comp.
// ---------------------------------------------------------------------------
#define HW0 (512*512)

__device__ float g_x0  [6*3*HW0];
__device__ float g_bufA[6*64*HW0];
__device__ float g_bufB[6*64*HW0];
__device__ float g_p1  [6*64*256*256];
__device__ float g_p2  [6*128*128*128];
__device__ float g_p3  [6*256*64*64];
__device__ double g_acc[4];   // 0:hole 1:valid 2:perc(raw) 3:style(scaled)

typedef unsigned long long u64;

// ---- packed f32x2 helpers (FFMA2: ptxas never emits these from C++) -------
__device__ __forceinline__ u64 pk(float lo, float hi) {
    u64 r; asm("mov.b64 %0,{%1,%2};" : "=l"(r) : "f"(lo), "f"(hi)); return r;
}
__device__ __forceinline__ float2 upk(u64 v) {
    float2 r; asm("mov.b64 {%0,%1},%2;" : "=f"(r.x), "=f"(r.y) : "l"(v)); return r;
}
__device__ __forceinline__ u64 fma2(u64 a, u64 b, u64 c) {
    u64 d; asm("fma.rn.f32x2 %0,%1,%2,%3;" : "=l"(d) : "l"(a), "l"(b), "l"(c)); return d;
}

// ---- cp.async helpers ------------------------------------------------------
__device__ __forceinline__ void cp4(uint32_t s, const float* g, bool ok) {
    asm volatile("cp.async.ca.shared.global [%0],[%1],4,%2;"
                 :: "r"(s), "l"(g), "r"(ok ? 4 : 0));
}
__device__ __forceinline__ void cp_commit() { asm volatile("cp.async.commit_group;"); }
template<int N> __device__ __forceinline__ void cp_wait() {
    asm volatile("cp.async.wait_group %0;" :: "n"(N));
}

// ---------------------------------------------------------------------------
__device__ __forceinline__ double blockReduceSum(double v) {
    __shared__ double s[32];
    int lane = threadIdx.x & 31, wid = threadIdx.x >> 5;
    #pragma unroll
    for (int o = 16; o; o >>= 1) v += __shfl_down_sync(0xffffffffu, v, o);
    if (lane == 0) s[wid] = v;
    __syncthreads();
    int nw = blockDim.x >> 5;
    v = (threadIdx.x < nw) ? s[threadIdx.x] : 0.0;
    if (wid == 0) {
        #pragma unroll
        for (int o = 16; o; o >>= 1) v += __shfl_down_sync(0xffffffffu, v, o);
    }
    return v;
}

__global__ void zero_acc() { if (threadIdx.x < 4) g_acc[threadIdx.x] = 0.0; }

// ---------------------------------------------------------------------------
__global__ void prep_kernel(const float* __restrict__ igt,
                            const float* __restrict__ iout,
                            const float* __restrict__ mask) {
    double hole = 0.0, valid = 0.0;
    const int total = 2*3*HW0;
    int stride = gridDim.x * blockDim.x;
    for (int i = blockIdx.x*blockDim.x + threadIdx.x; i < total; i += stride) {
        int hw = i % HW0;
        int t  = i / HW0;
        int b  = t / 3;
        float g  = igt[i];
        float o  = iout[i];
        float mv = mask[b*HW0 + hw];
        float ad = fabsf(o - g);
        bool m = (mv != 0.0f);
        if (m) valid += (double)ad; else hole += (double)ad;
        float comp = m ? g : o;
        g_x0[i]          = o;
        g_x0[i + 6*HW0]  = g;
        g_x0[i + 12*HW0] = comp;
    }
    hole  = blockReduceSum(hole);
    __syncthreads();
    valid = blockReduceSum(valid);
    if (threadIdx.x == 0) {
        atomicAdd(&g_acc[0], hole);
        atomicAdd(&g_acc[1], valid);
    }
}

// ---------------------------------------------------------------------------
// Direct 3x3 SAME conv + bias + ReLU via FFMA2 (f32x2), cp.async double buffer.
// Block 256 thr; tile 16h x 64w; 8 couts/block; thread: 4 px x 8 co.
// 4 input channels per pipelined stage.
// ---------------------------------------------------------------------------
__global__ __launch_bounds__(256, 2)
void conv3x3_relu(const float* __restrict__ in, const float* __restrict__ wgt,
                  const float* __restrict__ bias, float* __restrict__ out,
                  int CIN, int COUT, int S)
{
    __shared__ __align__(16) float s_in[2][4][18*68];
    __shared__ __align__(16) u64   s_w2[2][4][8][12];   // duplicated weight pairs

    const int tid = threadIdx.x;
    const int tx = tid & 15, ty = tid >> 4;
    const int ncog = COUT >> 3;
    const int n = blockIdx.z / ncog, cog = blockIdx.z - n*ncog;
    const int w0 = blockIdx.x*64, h0 = blockIdx.y*16;

    const float* inb = in  + (size_t)n*CIN*S*S;
    const float* wb  = wgt + (size_t)(cog*8)*CIN*9;

    u64 acc[8][2];
    #pragma unroll
    for (int co = 0; co < 8; co++) { acc[co][0] = 0ull; acc[co][1] = 0ull; }

    // ---- prologue: stage 0 fill + weights (sync) ----
    {
        int nc0 = CIN < 4 ? CIN : 4;
        uint32_t sb = (uint32_t)__cvta_generic_to_shared(&s_in[0][0][0]);
        int tot = nc0*1188;
        for (int i = tid; i < tot; i += 256) {
            int ci = i/1188, rem = i - ci*1188;
            int r = rem/66, c = rem - r*66;
            int h = h0 + r - 1, w = w0 + c - 1;
            bool ok = ((unsigned)h < (unsigned)S) & ((unsigned)w < (unsigned)S);
            const float* g = ok ? inb + ((size_t)ci*S + h)*S + w : inb;
            cp4(sb + (uint32_t)((ci*18 + r)*68 + c)*4u, g, ok);
        }
        cp_commit();
        int nw = nc0*72;
        if (tid < nw) {
            int co = tid/(nc0*9), rem = tid - co*nc0*9, ci = rem/9, k = rem - ci*9;
            float v = __ldg(wb + (size_t)co*CIN*9 + (size_t)ci*9 + k);
            s_w2[0][ci][co][k] = pk(v, v);
        }
        int t2 = tid + 256;
        if (t2 < nw) {
            int co = t2/(nc0*9), rem = t2 - co*nc0*9, ci = rem/9, k = rem - ci*9;
            float v = __ldg(wb + (size_t)co*CIN*9 + (size_t)ci*9 + k);
            s_w2[0][ci][co][k] = pk(v, v);
        }
    }

    int buf = 0;
    for (int c0 = 0; c0 < CIN; c0 += 4) {
        int c1 = c0 + 4;
        bool more = c1 < CIN;
        int nc1 = (CIN - c1) < 4 ? (CIN - c1) : 4;
        float wr0 = 0.f, wr1 = 0.f;

        if (more) {
            // prefetch next stage: data via cp.async, weights into regs
            uint32_t sb = (uint32_t)__cvta_generic_to_shared(&s_in[buf^1][0][0]);
            int tot = nc1*1188;
            for (int i = tid; i < tot; i += 256) {
                int ci = i/1188, rem = i - ci*1188;
                int r = rem/66, c = rem - r*66;
                int h = h0 + r - 1, w = w0 + c - 1;
                bool ok = ((unsigned)h < (unsigned)S) & ((unsigned)w < (unsigned)S);
                const float* g = ok ? inb + ((size_t)(c1+ci)*S + h)*S + w : inb;
                cp4(sb + (uint32_t)((ci*18 + r)*68 + c)*4u, g, ok);
            }
            cp_commit();
            int nw = nc1*72;
            if (tid < nw) {
                int co = tid/(nc1*9), rem = tid - co*nc1*9, ci = rem/9, k = rem - ci*9;
                wr0 = __ldg(wb + (size_t)co*CIN*9 + (size_t)(c1+ci)*9 + k);
            }
            int t2 = tid + 256;
            if (t2 < nw) {
                int co = t2/(nc1*9), rem = t2 - co*nc1*9, ci = rem/9, k = rem - ci*9;
                wr1 = __ldg(wb + (size_t)co*CIN*9 + (size_t)(c1+ci)*9 + k);
            }
        }
        if (more) cp_wait<1>(); else cp_wait<0>();
        __syncthreads();

        // ---- compute current stage ----
        int ncc = (CIN - c0) < 4 ? (CIN - c0) : 4;
        #pragma unroll
        for (int ci = 0; ci < 4; ci++) {
            if (ci < ncc) {
                u64 p[3][5];
                #pragma unroll
                for (int dy = 0; dy < 3; dy++) {
                    const float* row = &s_in[buf][ci][(ty+dy)*68 + tx*4];
                    float4 q = *(const float4*)row;
                    float v4 = row[4], v5 = row[5];
                    p[dy][0] = pk(q.x, q.y); p[dy][1] = pk(q.y, q.z);
                    p[dy][2] = pk(q.z, q.w); p[dy][3] = pk(q.w, v4);
                    p[dy][4] = pk(v4, v5);
                }
                #pragma unroll
                for (int co = 0; co < 8; co++) {
                    const u64* wr = s_w2[buf][ci][co];
                    ulonglong2 wA = *(const ulonglong2*)(wr + 0);
                    ulonglong2 wB = *(const ulonglong2*)(wr + 2);
                    ulonglong2 wC = *(const ulonglong2*)(wr + 4);
                    ulonglong2 wD = *(const ulonglong2*)(wr + 6);
                    u64 w8 = wr[8];
                    u64 wk[9] = {wA.x, wA.y, wB.x, wB.y, wC.x, wC.y, wD.x, wD.y, w8};
                    #pragma unroll
                    for (int k = 0; k < 9; k++) {
                        int dy = k/3, dx = k - dy*3;
                        acc[co][0] = fma2(p[dy][dx],   wk[k], acc[co][0]);
                        acc[co][1] = fma2(p[dy][dx+2], wk[k], acc[co][1]);
                    }
                }
            }
        }

        // store prefetched weights for next stage (disjoint smem vs compute)
        if (more) {
            int nw = nc1*72;
            if (tid < nw) {
                int co = tid/(nc1*9), rem = tid - co*nc1*9, ci = rem/9, k = rem - ci*9;
                s_w2[buf^1][ci][co][k] = pk(wr0, wr0);
            }
            int t2 = tid + 256;
            if (t2 < nw) {
                int co = t2/(nc1*9), rem = t2 - co*nc1*9, ci = rem/9, k = rem - ci*9;
                s_w2[buf^1][ci][co][k] = pk(wr1, wr1);
            }
        }
        __syncthreads();
        buf ^= 1;
    }

    const int h = h0 + ty, w = w0 + tx*4;
    #pragma unroll
    for (int co = 0; co < 8; co++) {
        float bv = bias[cog*8 + co];
        float2 a = upk(acc[co][0]), b = upk(acc[co][1]);
        float4 o;
        o.x = fmaxf(a.x + bv, 0.f); o.y = fmaxf(a.y + bv, 0.f);
        o.z = fmaxf(b.x + bv, 0.f); o.w = fmaxf(b.y + bv, 0.f);
        *(float4*)&out[((size_t)(n*COUT + cog*8 + co)*S + h)*S + w] = o;
    }
}

// ---------------------------------------------------------------------------
__global__ void maxpool2(const float* __restrict__ in, float* __restrict__ out,
                         int C, int S) {
    const int So = S >> 1;
    const size_t total = (size_t)6*C*So*So;
    const size_t stride = (size_t)gridDim.x * blockDim.x;
    for (size_t i = blockIdx.x*(size_t)blockDim.x + threadIdx.x; i < total; i += stride) {
        int x = (int)(i % So);
        size_t t = i / So;
        int y = (int)(t % So);
        size_t ncc = t / So;
        const float* p = in + (ncc*S + 2*y)*S + 2*x;
        out[i] = fmaxf(fmaxf(p[0], p[1]), fmaxf(p[S], p[S+1]));
    }
}

// ---------------------------------------------------------------------------
__global__ void perc_kernel(const float* __restrict__ p, int C, int S) {
    const size_t per = (size_t)C*S*S;
    const size_t total = 2*per;
    const size_t stride = (size_t)gridDim.x * blockDim.x;
    double s = 0.0;
    for (size_t i = blockIdx.x*(size_t)blockDim.x + threadIdx.x; i < total; i += stride) {
        float po = p[i];
        float pg = p[i + 2*per];
        float pc = p[i + 4*per];
        s += (double)(fabsf(po-pg) + fabsf(pc-pg));
    }
    s = blockReduceSum(s);
    if (threadIdx.x == 0) atomicAdd(&g_acc[2], s);
}

// ---------------------------------------------------------------------------
// Style Gram-difference, FFMA2 version. 64x64 (w,v) tile per block, 4x4 micro.
// ---------------------------------------------------------------------------
__global__ __launch_bounds__(256, 2)
void style_kernel(const float* __restrict__ p, int C, int S, int va, double scale) {
    const int tid = threadIdx.x;
    const int tx = tid & 15, ty = tid >> 4;
    const int bc = blockIdx.z;
    const int b = bc / C, c = bc - b*C;
    const int wt = blockIdx.y * 64;
    const int vt = blockIdx.x * 64;
    const float* A = p + ((size_t)((va*2+b)*C + c)) * S * S;
    const float* G = p + ((size_t)((2   +b)*C + c)) * S * S;

    __shared__ __align__(16) float s_aw[32][64], s_av[32][64];
    __shared__ __align__(16) float s_gw[32][64], s_gv[32][64];

    u64 accA[4][2], accG[4][2];
    #pragma unroll
    for (int i = 0; i < 4; i++) {
        accA[i][0]=0ull; accA[i][1]=0ull; accG[i][0]=0ull; accG[i][1]=0ull;
    }

    for (int k0 = 0; k0 < S; k0 += 32) {
        __syncthreads();
        for (int i = tid; i < 32*64; i += 256) {
            int kk = i >> 6, col = i & 63;
            size_t row = (size_t)(k0+kk)*S;
            s_aw[kk][col] = A[row + wt + col];
            s_av[kk][col] = A[row + vt + col];
            s_gw[kk][col] = G[row + wt + col];
            s_gv[kk][col] = G[row + vt + col];
        }
        __syncthreads();
        #pragma unroll 4
        for (int kk = 0; kk < 32; kk++) {
            float4 aw4 = *(const float4*)&s_aw[kk][ty*4];
            float4 gw4 = *(const float4*)&s_gw[kk][ty*4];
            ulonglong2 av = *(const ulonglong2*)&s_av[kk][tx*4];
            ulonglong2 gv = *(const ulonglong2*)&s_gv[kk][tx*4];
            u64 aw[4] = {pk(aw4.x,aw4.x), pk(aw4.y,aw4.y), pk(aw4.z,aw4.z), pk(aw4.w,aw4.w)};
            u64 gw[4] = {pk(gw4.x,gw4.x), pk(gw4.y,gw4.y), pk(gw4.z,gw4.z), pk(gw4.w,gw4.w)};
            #pragma unroll
            for (int i = 0; i < 4; i++) {
                accA[i][0] = fma2(aw[i], av.x, accA[i][0]);
                accA[i][1] = fma2(aw[i], av.y, accA[i][1]);
                accG[i][0] = fma2(gw[i], gv.x, accG[i][0]);
                accG[i][1] = fma2(gw[i], gv.y, accG[i][1]);
            }
        }
    }
    double s = 0.0;
    #pragma unroll
    for (int i = 0; i < 4; i++) {
        #pragma unroll
        for (int j = 0; j < 2; j++) {
            float2 a = upk(accA[i][j]), g = upk(accG[i][j]);
            s += (double)fabsf(a.x - g.x) + (double)fabsf(a.y - g.y);
        }
    }
    s = blockReduceSum(s);
    if (threadIdx.x == 0) atomicAdd(&g_acc[3], scale * s);
}

// ---------------------------------------------------------------------------
__global__ void finish_kernel(float* __restrict__ out) {
    const double N    = 3.0*512.0*512.0*2.0;
    const double Nigt = 2.0*64.0*256.0*256.0;
    double t = 2.0*g_acc[0]/N
             +     g_acc[1]/N
             +     g_acc[2]/Nigt
             +     g_acc[3];
    out[0] = (float)t;
}

// ---------------------------------------------------------------------------
extern "C" void kernel_launch(void* const* d_in, const int* in_sizes, int n_in,
                              void* d_out, int out_size) {
    const float* igt  = (const float*)d_in[0];
    const float* iout = (const float*)d_in[1];
    const float* mask = (const float*)d_in[2];
    const float* w[7]; const float* bs[7];
    for (int i = 0; i < 7; i++) {
        w[i]  = (const float*)d_in[3 + 2*i];
        bs[i] = (const float*)d_in[4 + 2*i];
    }

    float *x0, *bufA, *bufB, *p1, *p2, *p3;
    cudaGetSymbolAddress((void**)&x0,   g_x0);
    cudaGetSymbolAddress((void**)&bufA, g_bufA);
    cudaGetSymbolAddress((void**)&bufB, g_bufB);
    cudaGetSymbolAddress((void**)&p1,   g_p1);
    cudaGetSymbolAddress((void**)&p2,   g_p2);
    cudaGetSymbolAddress((void**)&p3,   g_p3);

    zero_acc<<<1, 32>>>();
    prep_kernel<<<2048, 256>>>(igt, iout, mask);

    conv3x3_relu<<<dim3(8,32, 48), 256>>>(x0,   w[0], bs[0], bufA,   3,  64, 512);
    conv3x3_relu<<<dim3(8,32, 48), 256>>>(bufA, w[1], bs[1], bufB,  64,  64, 512);
    maxpool2<<<4096, 256>>>(bufB, p1, 64, 512);
    conv3x3_relu<<<dim3(4,16, 96), 256>>>(p1,   w[2], bs[2], bufA,  64, 128, 256);
    conv3x3_relu<<<dim3(4,16, 96), 256>>>(bufA, w[3], bs[3], bufB, 128, 128, 256);
    maxpool2<<<2048, 256>>>(bufB, p2, 128, 256);
    conv3x3_relu<<<dim3(2, 8,192), 256>>>(p2,   w[4], bs[4], bufA, 128, 256, 128);
    conv3x3_relu<<<dim3(2, 8,192), 256>>>(bufA, w[5], bs[5], bufB, 256, 256, 128);
    conv3x3_relu<<<dim3(2, 8,192), 256>>>(bufB, w[6], bs[6], bufA, 256, 256, 128);
    maxpool2<<<1024, 256>>>(bufA, p3, 256, 128);

    perc_kernel<<<2048, 256>>>(p1,  64, 256);
    perc_kernel<<<2048, 256>>>(p2, 128, 128);
    perc_kernel<<<1024, 256>>>(p3, 256,  64);

    const double s1 = 1.0/((double)64 *256*256)/( 64.0* 64.0);
    const double s2 = 1.0/((double)128*128*128)/(128.0*128.0);
    const double s3 = 1.0/((double)256* 64* 64)/(256.0*256.0);
    style_kernel<<<dim3(4,4,128), 256>>>(p1,  64, 256, 2, s1);
    style_kernel<<<dim3(4,4,128), 256>>>(p1,  64, 256, 0, s1);
    style_kernel<<<dim3(2,2,256), 256>>>(p2, 128, 128, 2, s2);
    style_kernel<<<dim3(2,2,256), 256>>>(p2, 128, 128, 0, s2);
    style_kernel<<<dim3(1,1,512), 256>>>(p3, 256,  64, 2, s3);
    style_kernel<<<dim3(1,1,512), 256>>>(p3, 256,  64, 0, s3);

    finish_kernel<<<1, 1>>>((float*)d_out);
}

// round 3
// speedup vs baseline: 2.3952x; 1.3181x over previous
#include <cuda_runtime.h>
#include <math.h>
#include <stdint.h>

// ---------------------------------------------------------------------------
// B=2, H=W=512. Three variants (iout, igt, icomp) -> 6 NCHW images.
// n = v*2 + b, v: 0=out, 1=gt, 2=comp.
// ---------------------------------------------------------------------------
#define HW0 (512*512)

__device__ float g_x0  [6*3*HW0];
__device__ float g_bufA[6*64*HW0];
__device__ float g_bufB[6*64*HW0];
__device__ float g_p1  [6*64*256*256];
__device__ float g_p2  [6*128*128*128];
__device__ float g_p3  [6*256*64*64];
__device__ double g_acc[4];   // 0:hole 1:valid 2:perc(raw) 3:style(scaled)

typedef unsigned long long u64;

// ---- packed f32x2 helpers --------------------------------------------------
__device__ __forceinline__ u64 pk(float lo, float hi) {
    u64 r; asm("mov.b64 %0,{%1,%2};" : "=l"(r) : "f"(lo), "f"(hi)); return r;
}
__device__ __forceinline__ float2 upk(u64 v) {
    float2 r; asm("mov.b64 {%0,%1},%2;" : "=f"(r.x), "=f"(r.y) : "l"(v)); return r;
}
__device__ __forceinline__ u64 fma2(u64 a, u64 b, u64 c) {
    u64 d; asm("fma.rn.f32x2 %0,%1,%2,%3;" : "=l"(d) : "l"(a), "l"(b), "l"(c)); return d;
}

// ---- cp.async helpers ------------------------------------------------------
__device__ __forceinline__ void cp4(uint32_t s, const float* g, bool ok) {
    asm volatile("cp.async.ca.shared.global [%0],[%1],4,%2;"
                 :: "r"(s), "l"(g), "r"(ok ? 4 : 0));
}
__device__ __forceinline__ void cp_commit() { asm volatile("cp.async.commit_group;"); }
template<int N> __device__ __forceinline__ void cp_wait() {
    asm volatile("cp.async.wait_group %0;" :: "n"(N));
}

// ---------------------------------------------------------------------------
__device__ __forceinline__ double blockReduceSum(double v) {
    __shared__ double s[32];
    int lane = threadIdx.x & 31, wid = threadIdx.x >> 5;
    #pragma unroll
    for (int o = 16; o; o >>= 1) v += __shfl_down_sync(0xffffffffu, v, o);
    if (lane == 0) s[wid] = v;
    __syncthreads();
    int nw = blockDim.x >> 5;
    v = (threadIdx.x < nw) ? s[threadIdx.x] : 0.0;
    if (wid == 0) {
        #pragma unroll
        for (int o = 16; o; o >>= 1) v += __shfl_down_sync(0xffffffffu, v, o);
    }
    return v;
}

__global__ void zero_acc() { if (threadIdx.x < 4) g_acc[threadIdx.x] = 0.0; }

// ---------------------------------------------------------------------------
__global__ void prep_kernel(const float* __restrict__ igt,
                            const float* __restrict__ iout,
                            const float* __restrict__ mask) {
    double hole = 0.0, valid = 0.0;
    const int total = 2*3*HW0;
    int stride = gridDim.x * blockDim.x;
    for (int i = blockIdx.x*blockDim.x + threadIdx.x; i < total; i += stride) {
        int hw = i % HW0;
        int t  = i / HW0;
        int b  = t / 3;
        float g  = igt[i];
        float o  = iout[i];
        float mv = mask[b*HW0 + hw];
        float ad = fabsf(o - g);
        bool m = (mv != 0.0f);
        if (m) valid += (double)ad; else hole += (double)ad;
        float comp = m ? g : o;
        g_x0[i]          = o;
        g_x0[i + 6*HW0]  = g;
        g_x0[i + 12*HW0] = comp;
    }
    hole  = blockReduceSum(hole);
    __syncthreads();
    valid = blockReduceSum(valid);
    if (threadIdx.x == 0) {
        atomicAdd(&g_acc[0], hole);
        atomicAdd(&g_acc[1], valid);
    }
}

// ---------------------------------------------------------------------------
// Direct 3x3 conv + bias + ReLU. FFMA2 pairs over OUTPUT CHANNELS:
// lane pair = (co=2cp, co=2cp+1). Weight pairs pre-packed in smem at fill time
// (zero per-MAC packing ALU); pixel operand duplicated once per (ci,dy).
// Block 256 thr; tile 16h x 64w; 8 couts/block; thread: 4 px x 4 co-pairs.
// cp.async double buffer, 4 input channels per stage.
// ---------------------------------------------------------------------------
__global__ __launch_bounds__(256, 3)
void conv3x3_relu(const float* __restrict__ in, const float* __restrict__ wgt,
                  const float* __restrict__ bias, float* __restrict__ out,
                  int CIN, int COUT, int S)
{
    __shared__ __align__(16) float s_in[2][4][18*68];
    // [buf][ci][dy][cp][dx(0..2) + pad] : pk(w[2cp][k], w[2cp+1][k])
    __shared__ __align__(16) u64   s_w2[2][4][3][4][4];

    const int tid = threadIdx.x;
    const int tx = tid & 15, ty = tid >> 4;
    const int ncog = COUT >> 3;
    const int n = blockIdx.z / ncog, cog = blockIdx.z - n*ncog;
    const int w0 = blockIdx.x*64, h0 = blockIdx.y*16;

    const float* inb = in  + (size_t)n*CIN*S*S;
    const float* wb  = wgt + (size_t)(cog*8)*CIN*9;

    u64 acc[4][4];   // [co-pair][px]
    #pragma unroll
    for (int cp = 0; cp < 4; cp++) {
        acc[cp][0]=0ull; acc[cp][1]=0ull; acc[cp][2]=0ull; acc[cp][3]=0ull;
    }

    // ---- prologue: stage 0 fill ----
    {
        int nc0 = CIN < 4 ? CIN : 4;
        uint32_t sb = (uint32_t)__cvta_generic_to_shared(&s_in[0][0][0]);
        int tot = nc0*1188;
        for (int i = tid; i < tot; i += 256) {
            int ci = i/1188, rem = i - ci*1188;
            int r = rem/66, c = rem - r*66;
            int h = h0 + r - 1, w = w0 + c - 1;
            bool ok = ((unsigned)h < (unsigned)S) & ((unsigned)w < (unsigned)S);
            const float* g = ok ? inb + ((size_t)ci*S + h)*S + w : inb;
            cp4(sb + (uint32_t)((ci*18 + r)*68 + c)*4u, g, ok);
        }
        cp_commit();
        int nw = nc0*36;                       // (ci, cp, k) pairs, <=144
        if (tid < nw) {
            int cp = tid/(nc0*9), rem = tid - cp*nc0*9, ci = rem/9, k = rem - ci*9;
            int dy = k/3, dx = k - dy*3;
            float lo = __ldg(wb + (size_t)(2*cp  )*CIN*9 + (size_t)ci*9 + k);
            float hi = __ldg(wb + (size_t)(2*cp+1)*CIN*9 + (size_t)ci*9 + k);
            s_w2[0][ci][dy][cp][dx] = pk(lo, hi);
        }
    }

    int buf = 0;
    for (int c0 = 0; c0 < CIN; c0 += 4) {
        int c1 = c0 + 4;
        bool more = c1 < CIN;
        int nc1 = (CIN - c1) < 4 ? (CIN - c1) : 4;
        float wlo = 0.f, whi = 0.f;

        if (more) {
            uint32_t sb = (uint32_t)__cvta_generic_to_shared(&s_in[buf^1][0][0]);
            int tot = nc1*1188;
            for (int i = tid; i < tot; i += 256) {
                int ci = i/1188, rem = i - ci*1188;
                int r = rem/66, c = rem - r*66;
                int h = h0 + r - 1, w = w0 + c - 1;
                bool ok = ((unsigned)h < (unsigned)S) & ((unsigned)w < (unsigned)S);
                const float* g = ok ? inb + ((size_t)(c1+ci)*S + h)*S + w : inb;
                cp4(sb + (uint32_t)((ci*18 + r)*68 + c)*4u, g, ok);
            }
            cp_commit();
            int nw = nc1*36;
            if (tid < nw) {
                int cp = tid/(nc1*9), rem = tid - cp*nc1*9, ci = rem/9, k = rem - ci*9;
                wlo = __ldg(wb + (size_t)(2*cp  )*CIN*9 + (size_t)(c1+ci)*9 + k);
                whi = __ldg(wb + (size_t)(2*cp+1)*CIN*9 + (size_t)(c1+ci)*9 + k);
            }
        }
        if (more) cp_wait<1>(); else cp_wait<0>();
        __syncthreads();

        // ---- compute current stage ----
        int ncc = (CIN - c0) < 4 ? (CIN - c0) : 4;
        #pragma unroll
        for (int ci = 0; ci < 4; ci++) {
            if (ci < ncc) {
                #pragma unroll
                for (int dy = 0; dy < 3; dy++) {
                    const float* row = &s_in[buf][ci][(ty+dy)*68 + tx*4];
                    float4 q = *(const float4*)row;
                    float v4 = row[4], v5 = row[5];
                    u64 d0 = pk(q.x,q.x), d1 = pk(q.y,q.y), d2 = pk(q.z,q.z);
                    u64 d3 = pk(q.w,q.w), d4 = pk(v4,v4),   d5 = pk(v5,v5);
                    #pragma unroll
                    for (int cp = 0; cp < 4; cp++) {
                        const u64* wr = s_w2[buf][ci][dy][cp];
                        ulonglong2 w01 = *(const ulonglong2*)wr;
                        u64 w2v = wr[2];
                        // dx = 0
                        acc[cp][0] = fma2(d0, w01.x, acc[cp][0]);
                        acc[cp][1] = fma2(d1, w01.x, acc[cp][1]);
                        acc[cp][2] = fma2(d2, w01.x, acc[cp][2]);
                        acc[cp][3] = fma2(d3, w01.x, acc[cp][3]);
                        // dx = 1
                        acc[cp][0] = fma2(d1, w01.y, acc[cp][0]);
                        acc[cp][1] = fma2(d2, w01.y, acc[cp][1]);
                        acc[cp][2] = fma2(d3, w01.y, acc[cp][2]);
                        acc[cp][3] = fma2(d4, w01.y, acc[cp][3]);
                        // dx = 2
                        acc[cp][0] = fma2(d2, w2v, acc[cp][0]);
                        acc[cp][1] = fma2(d3, w2v, acc[cp][1]);
                        acc[cp][2] = fma2(d4, w2v, acc[cp][2]);
                        acc[cp][3] = fma2(d5, w2v, acc[cp][3]);
                    }
                }
            }
        }

        if (more) {
            int nw = nc1*36;
            if (tid < nw) {
                int cp = tid/(nc1*9), rem = tid - cp*nc1*9, ci = rem/9, k = rem - ci*9;
                int dy = k/3, dx = k - dy*3;
                s_w2[buf^1][ci][dy][cp][dx] = pk(wlo, whi);
            }
        }
        __syncthreads();
        buf ^= 1;
    }

    const int h = h0 + ty, w = w0 + tx*4;
    #pragma unroll
    for (int cp = 0; cp < 4; cp++) {
        float blo = bias[cog*8 + 2*cp], bhi = bias[cog*8 + 2*cp + 1];
        float2 a0 = upk(acc[cp][0]), a1 = upk(acc[cp][1]);
        float2 a2 = upk(acc[cp][2]), a3 = upk(acc[cp][3]);
        float4 olo, ohi;
        olo.x = fmaxf(a0.x + blo, 0.f); olo.y = fmaxf(a1.x + blo, 0.f);
        olo.z = fmaxf(a2.x + blo, 0.f); olo.w = fmaxf(a3.x + blo, 0.f);
        ohi.x = fmaxf(a0.y + bhi, 0.f); ohi.y = fmaxf(a1.y + bhi, 0.f);
        ohi.z = fmaxf(a2.y + bhi, 0.f); ohi.w = fmaxf(a3.y + bhi, 0.f);
        *(float4*)&out[((size_t)(n*COUT + cog*8 + 2*cp    )*S + h)*S + w] = olo;
        *(float4*)&out[((size_t)(n*COUT + cog*8 + 2*cp + 1)*S + h)*S + w] = ohi;
    }
}

// ---------------------------------------------------------------------------
__global__ void maxpool2(const float* __restrict__ in, float* __restrict__ out,
                         int C, int S) {
    const int So = S >> 1;
    const size_t total = (size_t)6*C*So*So;
    const size_t stride = (size_t)gridDim.x * blockDim.x;
    for (size_t i = blockIdx.x*(size_t)blockDim.x + threadIdx.x; i < total; i += stride) {
        int x = (int)(i % So);
        size_t t = i / So;
        int y = (int)(t % So);
        size_t ncc = t / So;
        const float* p = in + (ncc*S + 2*y)*S + 2*x;
        out[i] = fmaxf(fmaxf(p[0], p[1]), fmaxf(p[S], p[S+1]));
    }
}

// ---------------------------------------------------------------------------
__global__ void perc_kernel(const float* __restrict__ p, int C, int S) {
    const size_t per = (size_t)C*S*S;
    const size_t total = 2*per;
    const size_t stride = (size_t)gridDim.x * blockDim.x;
    double s = 0.0;
    for (size_t i = blockIdx.x*(size_t)blockDim.x + threadIdx.x; i < total; i += stride) {
        float po = p[i];
        float pg = p[i + 2*per];
        float pc = p[i + 4*per];
        s += (double)(fabsf(po-pg) + fabsf(pc-pg));
    }
    s = blockReduceSum(s);
    if (threadIdx.x == 0) atomicAdd(&g_acc[2], s);
}

// ---------------------------------------------------------------------------
// Style Gram-difference (FFMA2). 64x64 (w,v) tile per block, 4x4 micro.
// ---------------------------------------------------------------------------
__global__ __launch_bounds__(256, 2)
void style_kernel(const float* __restrict__ p, int C, int S, int va, double scale) {
    const int tid = threadIdx.x;
    const int tx = tid & 15, ty = tid >> 4;
    const int bc = blockIdx.z;
    const int b = bc / C, c = bc - b*C;
    const int wt = blockIdx.y * 64;
    const int vt = blockIdx.x * 64;
    const float* A = p + ((size_t)((va*2+b)*C + c)) * S * S;
    const float* G = p + ((size_t)((2   +b)*C + c)) * S * S;

    __shared__ __align__(16) float s_aw[32][64], s_av[32][64];
    __shared__ __align__(16) float s_gw[32][64], s_gv[32][64];

    u64 accA[4][2], accG[4][2];
    #pragma unroll
    for (int i = 0; i < 4; i++) {
        accA[i][0]=0ull; accA[i][1]=0ull; accG[i][0]=0ull; accG[i][1]=0ull;
    }

    for (int k0 = 0; k0 < S; k0 += 32) {
        __syncthreads();
        for (int i = tid; i < 32*64; i += 256) {
            int kk = i >> 6, col = i & 63;
            size_t row = (size_t)(k0+kk)*S;
            s_aw[kk][col] = A[row + wt + col];
            s_av[kk][col] = A[row + vt + col];
            s_gw[kk][col] = G[row + wt + col];
            s_gv[kk][col] = G[row + vt + col];
        }
        __syncthreads();
        #pragma unroll 4
        for (int kk = 0; kk < 32; kk++) {
            float4 aw4 = *(const float4*)&s_aw[kk][ty*4];
            float4 gw4 = *(const float4*)&s_gw[kk][ty*4];
            ulonglong2 av = *(const ulonglong2*)&s_av[kk][tx*4];
            ulonglong2 gv = *(const ulonglong2*)&s_gv[kk][tx*4];
            u64 aw[4] = {pk(aw4.x,aw4.x), pk(aw4.y,aw4.y), pk(aw4.z,aw4.z), pk(aw4.w,aw4.w)};
            u64 gw[4] = {pk(gw4.x,gw4.x), pk(gw4.y,gw4.y), pk(gw4.z,gw4.z), pk(gw4.w,gw4.w)};
            #pragma unroll
            for (int i = 0; i < 4; i++) {
                accA[i][0] = fma2(aw[i], av.x, accA[i][0]);
                accA[i][1] = fma2(aw[i], av.y, accA[i][1]);
                accG[i][0] = fma2(gw[i], gv.x, accG[i][0]);
                accG[i][1] = fma2(gw[i], gv.y, accG[i][1]);
            }
        }
    }
    double s = 0.0;
    #pragma unroll
    for (int i = 0; i < 4; i++) {
        #pragma unroll
        for (int j = 0; j < 2; j++) {
            float2 a = upk(accA[i][j]), g = upk(accG[i][j]);
            s += (double)fabsf(a.x - g.x) + (double)fabsf(a.y - g.y);
        }
    }
    s = blockReduceSum(s);
    if (threadIdx.x == 0) atomicAdd(&g_acc[3], scale * s);
}

// ---------------------------------------------------------------------------
__global__ void finish_kernel(float* __restrict__ out) {
    const double N    = 3.0*512.0*512.0*2.0;
    const double Nigt = 2.0*64.0*256.0*256.0;
    double t = 2.0*g_acc[0]/N
             +     g_acc[1]/N
             +     g_acc[2]/Nigt
             +     g_acc[3];
    out[0] = (float)t;
}

// ---------------------------------------------------------------------------
extern "C" void kernel_launch(void* const* d_in, const int* in_sizes, int n_in,
                              void* d_out, int out_size) {
    const float* igt  = (const float*)d_in[0];
    const float* iout = (const float*)d_in[1];
    const float* mask = (const float*)d_in[2];
    const float* w[7]; const float* bs[7];
    for (int i = 0; i < 7; i++) {
        w[i]  = (const float*)d_in[3 + 2*i];
        bs[i] = (const float*)d_in[4 + 2*i];
    }

    float *x0, *bufA, *bufB, *p1, *p2, *p3;
    cudaGetSymbolAddress((void**)&x0,   g_x0);
    cudaGetSymbolAddress((void**)&bufA, g_bufA);
    cudaGetSymbolAddress((void**)&bufB, g_bufB);
    cudaGetSymbolAddress((void**)&p1,   g_p1);
    cudaGetSymbolAddress((void**)&p2,   g_p2);
    cudaGetSymbolAddress((void**)&p3,   g_p3);

    zero_acc<<<1, 32>>>();
    prep_kernel<<<2048, 256>>>(igt, iout, mask);

    conv3x3_relu<<<dim3(8,32, 48), 256>>>(x0,   w[0], bs[0], bufA,   3,  64, 512);
    conv3x3_relu<<<dim3(8,32, 48), 256>>>(bufA, w[1], bs[1], bufB,  64,  64, 512);
    maxpool2<<<4096, 256>>>(bufB, p1, 64, 512);
    conv3x3_relu<<<dim3(4,16, 96), 256>>>(p1,   w[2], bs[2], bufA,  64, 128, 256);
    conv3x3_relu<<<dim3(4,16, 96), 256>>>(bufA, w[3], bs[3], bufB, 128, 128, 256);
    maxpool2<<<2048, 256>>>(bufB, p2, 128, 256);
    conv3x3_relu<<<dim3(2, 8,192), 256>>>(p2,   w[4], bs[4], bufA, 128, 256, 128);
    conv3x3_relu<<<dim3(2, 8,192), 256>>>(bufA, w[5], bs[5], bufB, 256, 256, 128);
    conv3x3_relu<<<dim3(2, 8,192), 256>>>(bufB, w[6], bs[6], bufA, 256, 256, 128);
    maxpool2<<<1024, 256>>>(bufA, p3, 256, 128);

    perc_kernel<<<2048, 256>>>(p1,  64, 256);
    perc_kernel<<<2048, 256>>>(p2, 128, 128);
    perc_kernel<<<1024, 256>>>(p3, 256,  64);

    const double s1 = 1.0/((double)64 *256*256)/( 64.0* 64.0);
    const double s2 = 1.0/((double)128*128*128)/(128.0*128.0);
    const double s3 = 1.0/((double)256* 64* 64)/(256.0*256.0);
    style_kernel<<<dim3(4,4,128), 256>>>(p1,  64, 256, 2, s1);
    style_kernel<<<dim3(4,4,128), 256>>>(p1,  64, 256, 0, s1);
    style_kernel<<<dim3(2,2,256), 256>>>(p2, 128, 128, 2, s2);
    style_kernel<<<dim3(2,2,256), 256>>>(p2, 128, 128, 0, s2);
    style_kernel<<<dim3(1,1,512), 256>>>(p3, 256,  64, 2, s3);
    style_kernel<<<dim3(1,1,512), 256>>>(p3, 256,  64, 0, s3);

    finish_kernel<<<1, 1>>>((float*)d_out);
}